// round 1
// baseline (speedup 1.0000x reference)
#include <cuda_runtime.h>

#define NP 131072
#define NS 16
#define C  256

// Scratch (static __device__ — no allocations allowed)
__device__ float g_sums[NS * C];   // per-segment channel sums
__device__ float g_z[NS * C];      // per-segment bias row z[s] = y[s]@W1b + b1
__device__ float g_bn[2 * C];      // [0:C) sum, [C:2C) sumsq of h
__device__ float g_sc[2 * C];      // [0:C) scale, [C:2C) shift

// ---------------- K1: zero accumulators (must reset every graph replay) ----
__global__ void k_zero() {
    int t = threadIdx.x;
    for (int i = t; i < NS * C; i += 256) g_sums[i] = 0.f;
    for (int i = t; i < 2 * C; i += 256) g_bn[i] = 0.f;
}

// ---------------- K2: ragged segment sums ---------------------------------
// 32 blocks per segment; block = 256 threads = one full channel row per iter.
__global__ void k_segsum(const float* __restrict__ x, const int* __restrict__ o) {
    int seg = blockIdx.x >> 5;
    int sub = blockIdx.x & 31;
    int t = threadIdx.x;
    int start = seg ? o[seg - 1] : 0;
    int end = o[seg];
    float acc = 0.f;
    #pragma unroll 4
    for (int r = start + sub; r < end; r += 32)
        acc += x[(size_t)r * C + t];
    atomicAdd(&g_sums[seg * C + t], acc);
}

// ---------------- K3: per-segment MLP -> z --------------------------------
__global__ void k_segmlp(const int* __restrict__ o,
                         const float* __restrict__ W1, const float* __restrict__ b1,
                         const float* __restrict__ W2, const float* __restrict__ b2) {
    __shared__ float m[C];
    __shared__ float y[C];
    int s = blockIdx.x, t = threadIdx.x;
    int start = s ? o[s - 1] : 0;
    float inv = 1.f / (float)(o[s] - start);
    m[t] = g_sums[s * C + t] * inv;
    __syncthreads();
    float acc = b2[t];
    #pragma unroll 8
    for (int k = 0; k < C; k++) acc = fmaf(m[k], W2[k * C + t], acc);
    y[t] = fmaxf(acc, 0.f);
    __syncthreads();
    float acc2 = b1[t];
    #pragma unroll 8
    for (int k = 0; k < C; k++) acc2 = fmaf(y[k], W1[(size_t)(C + k) * C + t], acc2);
    g_z[s * C + t] = acc2;
}

// ---------------- K4: h = x @ W1a + z[seg]  ->  d_out ---------------------
// Classic register-tiled SGEMM: BM=64, BN=64, BK=32, 4x4 per thread.
#define BM 64
#define BN 64
#define BK 32
__global__ __launch_bounds__(256) void k_mm(const float* __restrict__ x,
                                            const float* __restrict__ W1,
                                            const int* __restrict__ o,
                                            float* __restrict__ h) {
    __shared__ float As[BK][BM];   // x tile, transposed: [k][m]
    __shared__ float Bs[BK][BN];   // W tile: [k][n]
    __shared__ int so[NS];
    int t = threadIdx.x;
    if (t < NS) so[t] = o[t];
    int r0 = blockIdx.x * BM;
    int c0 = blockIdx.y * BN;
    int tx = t & 15, ty = t >> 4;
    float acc[4][4] = {};

    for (int kk = 0; kk < C; kk += BK) {
        #pragma unroll
        for (int i = 0; i < 2; i++) {
            int l = t + 256 * i;
            // x tile: 64 rows x 32 k = 512 float4 (row = l/8, 4-k-chunk = l%8)
            int row = l >> 3, fc = l & 7;
            float4 v = *(const float4*)&x[(size_t)(r0 + row) * C + kk + fc * 4];
            As[fc * 4 + 0][row] = v.x;
            As[fc * 4 + 1][row] = v.y;
            As[fc * 4 + 2][row] = v.z;
            As[fc * 4 + 3][row] = v.w;
            // W tile: 32 k-rows x 64 cols = 512 float4 (krow = l/16)
            int krow = l >> 4, fcb = l & 15;
            float4 w = *(const float4*)&W1[(size_t)(kk + krow) * C + c0 + fcb * 4];
            *(float4*)&Bs[krow][fcb * 4] = w;
        }
        __syncthreads();
        #pragma unroll
        for (int k = 0; k < BK; k++) {
            float a[4], b[4];
            #pragma unroll
            for (int i = 0; i < 4; i++) a[i] = As[k][ty * 4 + i];
            #pragma unroll
            for (int j = 0; j < 4; j++) b[j] = Bs[k][tx * 4 + j];
            #pragma unroll
            for (int i = 0; i < 4; i++)
                #pragma unroll
                for (int j = 0; j < 4; j++)
                    acc[i][j] = fmaf(a[i], b[j], acc[i][j]);
        }
        __syncthreads();
    }

    // epilogue: + z[seg][c], write h
    #pragma unroll
    for (int i = 0; i < 4; i++) {
        int r = r0 + ty * 4 + i;
        int seg = 0;
        #pragma unroll
        for (int s2 = 0; s2 < NS; s2++) seg += (r >= so[s2]);  // searchsorted right
        const float* zr = &g_z[seg * C + c0 + tx * 4];
        float4 outv;
        outv.x = acc[i][0] + zr[0];
        outv.y = acc[i][1] + zr[1];
        outv.z = acc[i][2] + zr[2];
        outv.w = acc[i][3] + zr[3];
        *(float4*)&h[(size_t)r * C + c0 + tx * 4] = outv;
    }
}

// ---------------- K5: BN column sums/sumsq --------------------------------
__global__ void k_bnred(const float* __restrict__ h) {
    int t = threadIdx.x;
    int base = blockIdx.x * (NP / 512);
    float s = 0.f, ss = 0.f;
    #pragma unroll 4
    for (int i = 0; i < NP / 512; i++) {
        float v = h[(size_t)(base + i) * C + t];
        s += v;
        ss = fmaf(v, v, ss);
    }
    atomicAdd(&g_bn[t], s);
    atomicAdd(&g_bn[C + t], ss);
}

// ---------------- K6: BN finalize -----------------------------------------
__global__ void k_bnfin(const float* __restrict__ gamma, const float* __restrict__ beta) {
    int t = threadIdx.x;
    float mu = g_bn[t] * (1.f / NP);
    float var = g_bn[C + t] * (1.f / NP) - mu * mu;
    float sc = gamma[t] * rsqrtf(var + 1e-5f);
    g_sc[t] = sc;
    g_sc[C + t] = beta[t] - mu * sc;
}

// ---------------- K7: out = relu(h*scale + shift), in place ---------------
__global__ void k_apply(float* __restrict__ h) {
    __shared__ float ssc[2 * C];
    int t = threadIdx.x;
    ssc[t] = g_sc[t];
    ssc[t + C] = g_sc[t + C];
    __syncthreads();
    size_t total = (size_t)NP * C / 4;
    for (size_t p = (size_t)blockIdx.x * 256 + t; p < total; p += (size_t)gridDim.x * 256) {
        float4 v = ((float4*)h)[p];
        int cb = (int)((p * 4) & (C - 1));
        v.x = fmaxf(fmaf(v.x, ssc[cb + 0], ssc[C + cb + 0]), 0.f);
        v.y = fmaxf(fmaf(v.y, ssc[cb + 1], ssc[C + cb + 1]), 0.f);
        v.z = fmaxf(fmaf(v.z, ssc[cb + 2], ssc[C + cb + 2]), 0.f);
        v.w = fmaxf(fmaf(v.w, ssc[cb + 3], ssc[C + cb + 3]), 0.f);
        ((float4*)h)[p] = v;
    }
}

extern "C" void kernel_launch(void* const* d_in, const int* in_sizes, int n_in,
                              void* d_out, int out_size) {
    const float* x     = (const float*)d_in[0];
    const int*   o     = (const int*)d_in[1];
    const float* W1    = (const float*)d_in[2];
    const float* b1    = (const float*)d_in[3];
    const float* W2    = (const float*)d_in[4];
    const float* b2    = (const float*)d_in[5];
    const float* gamma = (const float*)d_in[6];
    const float* beta  = (const float*)d_in[7];
    float* h = (float*)d_out;   // use d_out as scratch for h, finalize in place

    k_zero<<<1, 256>>>();
    k_segsum<<<512, 256>>>(x, o);
    k_segmlp<<<NS, 256>>>(o, W1, b1, W2, b2);
    dim3 g(NP / BM, C / BN);
    k_mm<<<g, 256>>>(x, W1, o, h);
    k_bnred<<<512, 256>>>(h);
    k_bnfin<<<1, 256>>>(gamma, beta);
    k_apply<<<2048, 256>>>(h);
}

// round 2
// speedup vs baseline: 2.0431x; 2.0431x over previous
#include <cuda_runtime.h>
#include <cstdint>

#define NP 131072
#define NS 16
#define C  256

// Scratch (static __device__ — no allocations allowed)
__device__ float g_sums[NS * C];   // per-segment channel sums
__device__ float g_z[NS * C];      // per-segment bias row z[s] = y[s]@W1b + b1
__device__ float g_bn[2 * C];      // [0:C) sum, [C:2C) sumsq of h
__device__ float g_sc[2 * C];      // [0:C) scale, [C:2C) shift

// ---------------- K1: zero accumulators -----------------------------------
__global__ void k_zero() {
    int t = threadIdx.x;
    for (int i = t; i < NS * C; i += 256) g_sums[i] = 0.f;
    for (int i = t; i < 2 * C; i += 256) g_bn[i] = 0.f;
}

// ---------------- K2: ragged segment sums ---------------------------------
__global__ void k_segsum(const float* __restrict__ x, const int* __restrict__ o) {
    int seg = blockIdx.x >> 5;
    int sub = blockIdx.x & 31;
    int t = threadIdx.x;
    int start = seg ? o[seg - 1] : 0;
    int end = o[seg];
    float acc = 0.f;
    #pragma unroll 4
    for (int r = start + sub; r < end; r += 32)
        acc += x[(size_t)r * C + t];
    atomicAdd(&g_sums[seg * C + t], acc);
}

// ---------------- K3: per-segment MLP -> z --------------------------------
__global__ void k_segmlp(const int* __restrict__ o,
                         const float* __restrict__ W1, const float* __restrict__ b1,
                         const float* __restrict__ W2, const float* __restrict__ b2) {
    __shared__ float m[C];
    __shared__ float y[C];
    int s = blockIdx.x, t = threadIdx.x;
    int start = s ? o[s - 1] : 0;
    float inv = 1.f / (float)(o[s] - start);
    m[t] = g_sums[s * C + t] * inv;
    __syncthreads();
    float acc = b2[t];
    #pragma unroll 8
    for (int k = 0; k < C; k++) acc = fmaf(m[k], W2[k * C + t], acc);
    y[t] = fmaxf(acc, 0.f);
    __syncthreads();
    float acc2 = b1[t];
    #pragma unroll 8
    for (int k = 0; k < C; k++) acc2 = fmaf(y[k], W1[(size_t)(C + k) * C + t], acc2);
    g_z[s * C + t] = acc2;
}

// ---------------- K4: h = x @ W1a + z[seg] via tf32 MMA; fused BN reduce ---
// Block tile 128x128, BK=32, 8 warps as 2(m) x 4(n), warp tile 64x32.
// Smem layouts are fragment-native: pairs (k, k+4) stored as uint2 (tf32 bits).
#define BM 128
#define BN 128
#define SA 520    // uint2 stride per k8-plane of As2 (512 + 8 pad)
#define RB 20     // uint2 per n-row of Bs2 (16 + 4 pad)

__device__ __forceinline__ unsigned f2tf(float f) {
    unsigned u;
    asm("cvt.rna.tf32.f32 %0, %1;" : "=r"(u) : "f"(f));
    return u;
}

__global__ __launch_bounds__(256, 2) void k_mm(const float* __restrict__ x,
                                               const float* __restrict__ W1,
                                               const int* __restrict__ o,
                                               float* __restrict__ h) {
    __shared__ uint2 As2[4 * SA];      // [k8-step][m(128) x kp(4)]
    __shared__ uint2 Bs2[128 * RB];    // [n(128)][k8-step(4) x kp(4)]
    __shared__ int so[NS];

    int tid = threadIdx.x;
    if (tid < NS) so[tid] = o[tid];
    int r0 = blockIdx.y * BM;
    int c0 = blockIdx.x * BN;
    int wid = tid >> 5, l = tid & 31, l4 = l >> 2, lm4 = l & 3;
    int wm = (wid & 1) * 64;     // warp m-offset
    int wn = (wid >> 1) * 32;    // warp n-offset

    float acc[4][4][4] = {};     // [mi][ni][frag]

    for (int kk = 0; kk < C; kk += 32) {
        __syncthreads();
        // ---- stage A & B (each thread: 2 tasks of each) ----
        #pragma unroll
        for (int i = 0; i < 2; i++) {
            int t = tid + i * 256;
            // A task: ks = t&3, m = t>>2 ; read 32B of x row, write paired layout
            {
                int ks = t & 3, m = t >> 2;
                const float4* gp = (const float4*)&x[(size_t)(r0 + m) * C + kk + ks * 8];
                float4 v0 = gp[0], v1 = gp[1];
                uint4* dp = (uint4*)&As2[ks * SA + m * 4];
                dp[0] = make_uint4(f2tf(v0.x), f2tf(v1.x), f2tf(v0.y), f2tf(v1.y));
                dp[1] = make_uint4(f2tf(v0.z), f2tf(v1.z), f2tf(v0.w), f2tf(v1.w));
            }
            // B task: kp = t&3, ks = (t>>2)&3, nc = t>>4 ; W rows k1, k1+4
            {
                int kp = t & 3, ks = (t >> 2) & 3, nc = t >> 4;
                int k1 = kk + ks * 8 + kp;
                float4 w0 = *(const float4*)&W1[(size_t)k1 * C + c0 + nc * 4];
                float4 w1 = *(const float4*)&W1[(size_t)(k1 + 4) * C + c0 + nc * 4];
                int nb = nc * 4;
                Bs2[(nb + 0) * RB + ks * 4 + kp] = make_uint2(f2tf(w0.x), f2tf(w1.x));
                Bs2[(nb + 1) * RB + ks * 4 + kp] = make_uint2(f2tf(w0.y), f2tf(w1.y));
                Bs2[(nb + 2) * RB + ks * 4 + kp] = make_uint2(f2tf(w0.z), f2tf(w1.z));
                Bs2[(nb + 3) * RB + ks * 4 + kp] = make_uint2(f2tf(w0.w), f2tf(w1.w));
            }
        }
        __syncthreads();

        // ---- 4 k8-steps of MMA ----
        #pragma unroll
        for (int ks = 0; ks < 4; ks++) {
            uint2 af[4][2];
            uint2 bf[4];
            #pragma unroll
            for (int mi = 0; mi < 4; mi++) {
                int row = wm + mi * 16 + l4;
                af[mi][0] = As2[ks * SA + row * 4 + lm4];        // (a0, a2)
                af[mi][1] = As2[ks * SA + (row + 8) * 4 + lm4];  // (a1, a3)
            }
            #pragma unroll
            for (int ni = 0; ni < 4; ni++)
                bf[ni] = Bs2[(wn + ni * 8 + l4) * RB + ks * 4 + lm4];  // (b0, b1)
            #pragma unroll
            for (int mi = 0; mi < 4; mi++)
                #pragma unroll
                for (int ni = 0; ni < 4; ni++)
                    asm volatile(
                        "mma.sync.aligned.m16n8k8.row.col.f32.tf32.tf32.f32 "
                        "{%0,%1,%2,%3},{%4,%5,%6,%7},{%8,%9},{%0,%1,%2,%3};"
                        : "+f"(acc[mi][ni][0]), "+f"(acc[mi][ni][1]),
                          "+f"(acc[mi][ni][2]), "+f"(acc[mi][ni][3])
                        : "r"(af[mi][0].x), "r"(af[mi][1].x),
                          "r"(af[mi][0].y), "r"(af[mi][1].y),
                          "r"(bf[ni].x), "r"(bf[ni].y));
        }
    }

    // ---- epilogue: + z[seg], write h, fused BN partial sums ----
    float cs[4][2] = {}, css[4][2] = {};
    #pragma unroll
    for (int mi = 0; mi < 4; mi++) {
        #pragma unroll
        for (int half = 0; half < 2; half++) {
            int r = r0 + wm + mi * 16 + l4 + half * 8;
            int seg = 0;
            #pragma unroll
            for (int s = 0; s < NS; s++) seg += (r >= so[s]);
            #pragma unroll
            for (int ni = 0; ni < 4; ni++) {
                int c = c0 + wn + ni * 8 + 2 * lm4;
                float2 z2 = *(const float2*)&g_z[seg * C + c];
                float v0 = acc[mi][ni][half * 2 + 0] + z2.x;
                float v1 = acc[mi][ni][half * 2 + 1] + z2.y;
                *(float2*)&h[(size_t)r * C + c] = make_float2(v0, v1);
                cs[ni][0] += v0;  cs[ni][1] += v1;
                css[ni][0] = fmaf(v0, v0, css[ni][0]);
                css[ni][1] = fmaf(v1, v1, css[ni][1]);
            }
        }
    }
    // reduce over the 8 row-groups (lanes differing in l4)
    #pragma unroll
    for (int ni = 0; ni < 4; ni++)
        #pragma unroll
        for (int j = 0; j < 2; j++)
            #pragma unroll
            for (int off = 4; off < 32; off <<= 1) {
                cs[ni][j]  += __shfl_xor_sync(0xffffffff, cs[ni][j],  off);
                css[ni][j] += __shfl_xor_sync(0xffffffff, css[ni][j], off);
            }
    if (l4 == 0) {
        #pragma unroll
        for (int ni = 0; ni < 4; ni++) {
            int c = c0 + wn + ni * 8 + 2 * lm4;
            atomicAdd(&g_bn[c],     cs[ni][0]);
            atomicAdd(&g_bn[c + 1], cs[ni][1]);
            atomicAdd(&g_bn[C + c],     css[ni][0]);
            atomicAdd(&g_bn[C + c + 1], css[ni][1]);
        }
    }
}

// ---------------- K6: BN finalize -----------------------------------------
__global__ void k_bnfin(const float* __restrict__ gamma, const float* __restrict__ beta) {
    int t = threadIdx.x;
    float mu = g_bn[t] * (1.f / NP);
    float var = g_bn[C + t] * (1.f / NP) - mu * mu;
    float sc = gamma[t] * rsqrtf(var + 1e-5f);
    g_sc[t] = sc;
    g_sc[C + t] = beta[t] - mu * sc;
}

// ---------------- K7: out = relu(h*scale + shift), in place ---------------
__global__ void k_apply(float* __restrict__ h) {
    __shared__ float ssc[2 * C];
    int t = threadIdx.x;
    ssc[t] = g_sc[t];
    ssc[t + C] = g_sc[t + C];
    __syncthreads();
    size_t total = (size_t)NP * C / 4;
    for (size_t p = (size_t)blockIdx.x * 256 + t; p < total; p += (size_t)gridDim.x * 256) {
        float4 v = ((float4*)h)[p];
        int cb = (int)((p * 4) & (C - 1));
        v.x = fmaxf(fmaf(v.x, ssc[cb + 0], ssc[C + cb + 0]), 0.f);
        v.y = fmaxf(fmaf(v.y, ssc[cb + 1], ssc[C + cb + 1]), 0.f);
        v.z = fmaxf(fmaf(v.z, ssc[cb + 2], ssc[C + cb + 2]), 0.f);
        v.w = fmaxf(fmaf(v.w, ssc[cb + 3], ssc[C + cb + 3]), 0.f);
        ((float4*)h)[p] = v;
    }
}

extern "C" void kernel_launch(void* const* d_in, const int* in_sizes, int n_in,
                              void* d_out, int out_size) {
    const float* x     = (const float*)d_in[0];
    const int*   o     = (const int*)d_in[1];
    const float* W1    = (const float*)d_in[2];
    const float* b1    = (const float*)d_in[3];
    const float* W2    = (const float*)d_in[4];
    const float* b2    = (const float*)d_in[5];
    const float* gamma = (const float*)d_in[6];
    const float* beta  = (const float*)d_in[7];
    float* h = (float*)d_out;

    k_zero<<<1, 256>>>();
    k_segsum<<<512, 256>>>(x, o);
    k_segmlp<<<NS, 256>>>(o, W1, b1, W2, b2);
    dim3 g(C / BN, NP / BM);   // n-major so both n-blocks of a row-tile share L2
    k_mm<<<g, 256>>>(x, W1, o, h);
    k_bnfin<<<1, 256>>>(gamma, beta);
    k_apply<<<2048, 256>>>(h);
}

// round 4
// speedup vs baseline: 2.4824x; 1.2150x over previous
#include <cuda_runtime.h>
#include <cstdint>

#define NP 131072
#define NS 16
#define C  256

// ------------------------------- scratch ----------------------------------
__device__ float g_wt[C * C];    // g_wt[n*C+k] = rna(W1[k*C+n])  (W1a^T, tf32-rounded)
__device__ float g_sums[NS * C];
__device__ float g_z[NS * C];
__device__ float g_bn[2 * C];
__device__ float g_sc[2 * C];

// ------------------------------- helpers ----------------------------------
__device__ __forceinline__ float tf32r(float f) {
    unsigned u;
    asm("cvt.rna.tf32.f32 %0, %1;" : "=r"(u) : "f"(f));
    return __uint_as_float(u);
}
__device__ __forceinline__ unsigned tf32u(float f) {
    unsigned u;
    asm("cvt.rna.tf32.f32 %0, %1;" : "=r"(u) : "f"(f));
    return u;
}
__device__ __forceinline__ uint32_t s2u(const void* p) {
    uint32_t a;
    asm("{ .reg .u64 t; cvta.to.shared.u64 t, %1; cvt.u32.u64 %0, t; }" : "=r"(a) : "l"(p));
    return a;
}
__device__ __forceinline__ void cpa16(uint32_t dst, const void* src) {
    asm volatile("cp.async.cg.shared.global [%0], [%1], 16;" :: "r"(dst), "l"(src));
}

// ---------------- K1: zero accumulators -----------------------------------
__global__ void k_zero() {
    int t = threadIdx.x;
    for (int i = t; i < NS * C; i += 256) g_sums[i] = 0.f;
    for (int i = t; i < 2 * C; i += 256) g_bn[i] = 0.f;
}

// ---------------- K2: ragged segment sums ---------------------------------
__global__ void k_segsum(const float* __restrict__ x, const int* __restrict__ o) {
    int seg = blockIdx.x >> 5;
    int sub = blockIdx.x & 31;
    int t = threadIdx.x;
    int start = seg ? o[seg - 1] : 0;
    int end = o[seg];
    float acc = 0.f;
    #pragma unroll 4
    for (int r = start + sub; r < end; r += 32)
        acc += x[(size_t)r * C + t];
    atomicAdd(&g_sums[seg * C + t], acc);
}

// ---------------- K2b: W1a^T, tf32-rounded --------------------------------
__global__ void k_wt(const float* __restrict__ W1) {
    __shared__ float tl[32][33];
    int k0 = blockIdx.x * 32, n0 = blockIdx.y * 32;
    int tx = threadIdx.x, ty = threadIdx.y;
    #pragma unroll
    for (int i = 0; i < 32; i += 8)
        tl[ty + i][tx] = W1[(size_t)(k0 + ty + i) * C + n0 + tx];
    __syncthreads();
    #pragma unroll
    for (int i = 0; i < 32; i += 8)
        g_wt[(size_t)(n0 + ty + i) * C + k0 + tx] = tf32r(tl[tx][ty + i]);
}

// ---------------- K3: per-segment MLP -> z --------------------------------
__global__ void k_segmlp(const int* __restrict__ o,
                         const float* __restrict__ W1, const float* __restrict__ b1,
                         const float* __restrict__ W2, const float* __restrict__ b2) {
    __shared__ float m[C];
    __shared__ float y[C];
    int s = blockIdx.x, t = threadIdx.x;
    int start = s ? o[s - 1] : 0;
    float inv = 1.f / (float)(o[s] - start);
    m[t] = g_sums[s * C + t] * inv;
    __syncthreads();
    float acc = b2[t];
    #pragma unroll 8
    for (int k = 0; k < C; k++) acc = fmaf(m[k], W2[k * C + t], acc);
    y[t] = fmaxf(acc, 0.f);
    __syncthreads();
    float acc2 = b1[t];
    #pragma unroll 8
    for (int k = 0; k < C; k++) acc2 = fmaf(y[k], W1[(size_t)(C + k) * C + t], acc2);
    g_z[s * C + t] = acc2;
}

// ---------------- K4: tf32 mma.sync GEMM, cp.async double-buffered ---------
// 128x128 block tile, BK=32, 8 warps (2m x 4n), warp tile 64x32.
// Smem: A[2][128][32] + B[2][128][32] floats, 128B rows, SW128 XOR swizzle.
// Swizzled word index for element (r, k): r*32 + (k ^ ((r&7)*4)).
#define BM 128
#define BN 128

__device__ __forceinline__ int sidx(int r, int k) {
    return r * 32 + (k ^ ((r & 7) * 4));
}

__global__ __launch_bounds__(256, 2) void k_mm(const float* __restrict__ x,
                                               const int* __restrict__ o,
                                               float* __restrict__ h) {
    extern __shared__ __align__(128) float smem[];  // 16384 floats = 64KB
    __shared__ int so[NS];
    __shared__ float shbn[512];

    uint32_t sb = s2u(smem);
    int tid = threadIdx.x;
    int w = tid >> 5, lane = tid & 31;
    int l4 = lane >> 2, lm4 = lane & 3;
    int wm = (w & 1) * 64;
    int wn = (w >> 1) * 32;
    int r0 = blockIdx.y * BM;
    int c0 = blockIdx.x * BN;

    if (tid < NS) so[tid] = o[tid];
    shbn[tid] = 0.f;
    shbn[tid + 256] = 0.f;

    // staging: tile kt -> buffer kt&1 (A and B, 4 x 16B cp.async each)
    auto stage = [&](int kt) {
        int buf = kt & 1;
        const float* xs = x + (size_t)r0 * C + kt * 32;
        const float* ws = g_wt + (size_t)c0 * C + kt * 32;
        uint32_t ab = sb + buf * 16384;
        uint32_t bb = sb + 32768 + buf * 16384;
        #pragma unroll
        for (int i = 0; i < 4; i++) {
            int cid = tid + i * 256;            // 1024 chunks of 16B
            int row = cid >> 3, c16 = cid & 7;
            uint32_t off = row * 128 + ((c16 * 16) ^ ((row & 7) * 16));
            cpa16(ab + off, xs + (size_t)row * C + c16 * 4);
            cpa16(bb + off, ws + (size_t)row * C + c16 * 4);
        }
        asm volatile("cp.async.commit_group;" ::: "memory");
    };

    float acc[4][4][4] = {};
    stage(0);

    for (int kt = 0; kt < 8; kt++) {
        if (kt < 7) {
            stage(kt + 1);
            asm volatile("cp.async.wait_group 1;" ::: "memory");
        } else {
            asm volatile("cp.async.wait_group 0;" ::: "memory");
        }
        __syncthreads();

        const float* A = smem + (kt & 1) * 4096;
        const float* B = smem + 8192 + (kt & 1) * 4096;

        #pragma unroll
        for (int ks = 0; ks < 4; ks++) {
            int kb = ks * 8 + lm4;
            unsigned af[4][4];
            unsigned bf[4][2];
            #pragma unroll
            for (int mi = 0; mi < 4; mi++) {
                int m0 = wm + mi * 16 + l4;
                af[mi][0] = tf32u(A[sidx(m0,     kb)]);
                af[mi][1] = tf32u(A[sidx(m0 + 8, kb)]);
                af[mi][2] = tf32u(A[sidx(m0,     kb + 4)]);
                af[mi][3] = tf32u(A[sidx(m0 + 8, kb + 4)]);
            }
            #pragma unroll
            for (int ni = 0; ni < 4; ni++) {
                int n = wn + ni * 8 + l4;
                bf[ni][0] = __float_as_uint(B[sidx(n, kb)]);
                bf[ni][1] = __float_as_uint(B[sidx(n, kb + 4)]);
            }
            #pragma unroll
            for (int mi = 0; mi < 4; mi++)
                #pragma unroll
                for (int ni = 0; ni < 4; ni++)
                    asm volatile(
                        "mma.sync.aligned.m16n8k8.row.col.f32.tf32.tf32.f32 "
                        "{%0,%1,%2,%3},{%4,%5,%6,%7},{%8,%9},{%0,%1,%2,%3};"
                        : "+f"(acc[mi][ni][0]), "+f"(acc[mi][ni][1]),
                          "+f"(acc[mi][ni][2]), "+f"(acc[mi][ni][3])
                        : "r"(af[mi][0]), "r"(af[mi][1]),
                          "r"(af[mi][2]), "r"(af[mi][3]),
                          "r"(bf[ni][0]), "r"(bf[ni][1]));
        }
        __syncthreads();   // protect buf kt&1 from stage(kt+2)
    }

    // ---- epilogue: + z[seg], write h, fused BN partial sums ----
    float cs[4][2] = {}, css[4][2] = {};
    #pragma unroll
    for (int mi = 0; mi < 4; mi++) {
        #pragma unroll
        for (int half = 0; half < 2; half++) {
            int r = r0 + wm + mi * 16 + l4 + half * 8;
            int seg = 0;
            #pragma unroll
            for (int s = 0; s < NS; s++) seg += (r >= so[s]);
            #pragma unroll
            for (int ni = 0; ni < 4; ni++) {
                int c = c0 + wn + ni * 8 + 2 * lm4;
                float2 z2 = *(const float2*)&g_z[seg * C + c];
                float v0 = acc[mi][ni][half * 2 + 0] + z2.x;
                float v1 = acc[mi][ni][half * 2 + 1] + z2.y;
                *(float2*)&h[(size_t)r * C + c] = make_float2(v0, v1);
                cs[ni][0] += v0;  cs[ni][1] += v1;
                css[ni][0] = fmaf(v0, v0, css[ni][0]);
                css[ni][1] = fmaf(v1, v1, css[ni][1]);
            }
        }
    }
    #pragma unroll
    for (int ni = 0; ni < 4; ni++)
        #pragma unroll
        for (int j = 0; j < 2; j++)
            #pragma unroll
            for (int off = 4; off < 32; off <<= 1) {
                cs[ni][j]  += __shfl_xor_sync(0xffffffff, cs[ni][j],  off);
                css[ni][j] += __shfl_xor_sync(0xffffffff, css[ni][j], off);
            }
    if (l4 == 0) {
        #pragma unroll
        for (int ni = 0; ni < 4; ni++) {
            int c = wn + ni * 8 + 2 * lm4;          // local column in [0,256)
            atomicAdd(&shbn[c],     cs[ni][0]);
            atomicAdd(&shbn[c + 1], cs[ni][1]);
            atomicAdd(&shbn[256 + c],     css[ni][0]);
            atomicAdd(&shbn[256 + c + 1], css[ni][1]);
        }
    }
    __syncthreads();
    atomicAdd(&g_bn[c0 + tid % 256 - (tid % 256 >= 256 ? 256 : 0)], 0.f); // (no-op guard)
    atomicAdd(&g_bn[c0 + tid], shbn[tid]);
    atomicAdd(&g_bn[C + c0 + tid], shbn[256 + tid]);
}

// ---------------- K6: BN finalize -----------------------------------------
__global__ void k_bnfin(const float* __restrict__ gamma, const float* __restrict__ beta) {
    int t = threadIdx.x;
    float mu = g_bn[t] * (1.f / NP);
    float var = g_bn[C + t] * (1.f / NP) - mu * mu;
    float sc = gamma[t] * rsqrtf(var + 1e-5f);
    g_sc[t] = sc;
    g_sc[C + t] = beta[t] - mu * sc;
}

// ---------------- K7: out = relu(h*scale + shift), in place ---------------
__global__ void k_apply(float* __restrict__ h) {
    __shared__ float ssc[2 * C];
    int t = threadIdx.x;
    ssc[t] = g_sc[t];
    ssc[t + C] = g_sc[t + C];
    __syncthreads();
    size_t total = (size_t)NP * C / 4;
    for (size_t p = (size_t)blockIdx.x * 256 + t; p < total; p += (size_t)gridDim.x * 256) {
        float4 v = ((float4*)h)[p];
        int cb = (int)((p * 4) & (C - 1));
        v.x = fmaxf(fmaf(v.x, ssc[cb + 0], ssc[C + cb + 0]), 0.f);
        v.y = fmaxf(fmaf(v.y, ssc[cb + 1], ssc[C + cb + 1]), 0.f);
        v.z = fmaxf(fmaf(v.z, ssc[cb + 2], ssc[C + cb + 2]), 0.f);
        v.w = fmaxf(fmaf(v.w, ssc[cb + 3], ssc[C + cb + 3]), 0.f);
        ((float4*)h)[p] = v;
    }
}

extern "C" void kernel_launch(void* const* d_in, const int* in_sizes, int n_in,
                              void* d_out, int out_size) {
    const float* x     = (const float*)d_in[0];
    const int*   o     = (const int*)d_in[1];
    const float* W1    = (const float*)d_in[2];
    const float* b1    = (const float*)d_in[3];
    const float* W2    = (const float*)d_in[4];
    const float* b2    = (const float*)d_in[5];
    const float* gamma = (const float*)d_in[6];
    const float* beta  = (const float*)d_in[7];
    float* h = (float*)d_out;

    static bool attr_done = false;
    if (!attr_done) {
        cudaFuncSetAttribute(k_mm, cudaFuncAttributeMaxDynamicSharedMemorySize, 65536);
        attr_done = true;
    }

    k_zero<<<1, 256>>>();
    k_segsum<<<512, 256>>>(x, o);
    k_wt<<<dim3(8, 8), dim3(32, 8)>>>(W1);
    k_segmlp<<<NS, 256>>>(o, W1, b1, W2, b2);
    dim3 g(C / BN, NP / BM);    // n-major: both n-blocks of a row-tile adjacent
    k_mm<<<g, 256, 65536>>>(x, o, h);
    k_bnfin<<<1, 256>>>(gamma, beta);
    k_apply<<<2048, 256>>>(h);
}

// round 5
// speedup vs baseline: 2.7598x; 1.1118x over previous
#include <cuda_runtime.h>
#include <cstdint>

#define NP 131072
#define NS 16
#define C  256

// ------------------------------- scratch ----------------------------------
__device__ float g_wt[C * C];          // g_wt[n*C+k] = rna(W1[k*C+n]) (W1a^T, tf32)
__device__ float g_part[NS * 32 * C];  // per-(seg,sub) partial sums
__device__ float g_y[NS * C];          // y = relu(means@W2 + b2)
__device__ float g_z[NS * C];          // z = y@W1b + b1
__device__ float g_bn[2 * C];
__device__ float g_sc[2 * C];

// ------------------------------- helpers ----------------------------------
__device__ __forceinline__ float tf32r(float f) {
    unsigned u;
    asm("cvt.rna.tf32.f32 %0, %1;" : "=r"(u) : "f"(f));
    return __uint_as_float(u);
}
__device__ __forceinline__ unsigned tf32u(float f) {
    unsigned u;
    asm("cvt.rna.tf32.f32 %0, %1;" : "=r"(u) : "f"(f));
    return u;
}
__device__ __forceinline__ uint32_t s2u(const void* p) {
    uint32_t a;
    asm("{ .reg .u64 t; cvta.to.shared.u64 t, %1; cvt.u32.u64 %0, t; }" : "=r"(a) : "l"(p));
    return a;
}
__device__ __forceinline__ void cpa16(uint32_t dst, const void* src) {
    asm volatile("cp.async.cg.shared.global [%0], [%1], 16;" :: "r"(dst), "l"(src));
}

// ---------------- K2: ragged segment partial sums (no atomics) -------------
__global__ void k_segsum(const float* __restrict__ x, const int* __restrict__ o) {
    int seg = blockIdx.x >> 5;
    int sub = blockIdx.x & 31;
    int t = threadIdx.x;
    int start = seg ? o[seg - 1] : 0;
    int end = o[seg];
    float acc = 0.f;
    #pragma unroll 4
    for (int r = start + sub; r < end; r += 32)
        acc += x[(size_t)r * C + t];
    g_part[(size_t)blockIdx.x * C + t] = acc;
}

// ---------------- K2b: W1a^T tf32-rounded; block 0 zeroes g_bn ------------
__global__ void k_wt(const float* __restrict__ W1) {
    __shared__ float tl[32][33];
    int k0 = blockIdx.x * 32, n0 = blockIdx.y * 32;
    int tx = threadIdx.x, ty = threadIdx.y;
    if (blockIdx.x == 0 && blockIdx.y == 0) {
        int t = ty * 32 + tx;
        g_bn[t] = 0.f;
        g_bn[t + 256] = 0.f;
    }
    #pragma unroll
    for (int i = 0; i < 32; i += 8)
        tl[ty + i][tx] = W1[(size_t)(k0 + ty + i) * C + n0 + tx];
    __syncthreads();
    #pragma unroll
    for (int i = 0; i < 32; i += 8)
        g_wt[(size_t)(n0 + ty + i) * C + k0 + tx] = tf32r(tl[tx][ty + i]);
}

// ---------------- K3a: y = relu(means @ W2 + b2) ---------------------------
// grid = NS*32 blocks; block computes mean into smem, then 8 warps x 1 channel.
__global__ __launch_bounds__(256) void k_mlp1(const int* __restrict__ o,
                                              const float* __restrict__ W2,
                                              const float* __restrict__ b2) {
    __shared__ float m[C];
    int seg = blockIdx.x >> 5;
    int cb = blockIdx.x & 31;      // channel block (8 channels)
    int t = threadIdx.x, w = t >> 5, lane = t & 31;
    int start = seg ? o[seg - 1] : 0;
    float inv = 1.f / (float)(o[seg] - start);
    float s = 0.f;
    #pragma unroll
    for (int sub = 0; sub < 32; sub++)
        s += g_part[(size_t)(seg * 32 + sub) * C + t];
    m[t] = s * inv;
    __syncthreads();
    int c = cb * 8 + w;
    float acc = 0.f;
    #pragma unroll
    for (int j = 0; j < 8; j++) {
        int k = lane + 32 * j;
        acc = fmaf(m[k], __ldg(&W2[(size_t)k * C + c]), acc);
    }
    #pragma unroll
    for (int off = 16; off; off >>= 1) acc += __shfl_xor_sync(0xffffffffu, acc, off);
    if (lane == 0) g_y[seg * C + c] = fmaxf(acc + b2[c], 0.f);
}

// ---------------- K3b: z = y @ W1b + b1 ------------------------------------
__global__ __launch_bounds__(256) void k_mlp2(const float* __restrict__ W1,
                                              const float* __restrict__ b1) {
    __shared__ float y[C];
    int seg = blockIdx.x >> 5;
    int cb = blockIdx.x & 31;
    int t = threadIdx.x, w = t >> 5, lane = t & 31;
    y[t] = g_y[seg * C + t];
    __syncthreads();
    int c = cb * 8 + w;
    float acc = 0.f;
    #pragma unroll
    for (int j = 0; j < 8; j++) {
        int k = lane + 32 * j;
        acc = fmaf(y[k], __ldg(&W1[(size_t)(C + k) * C + c]), acc);
    }
    #pragma unroll
    for (int off = 16; off; off >>= 1) acc += __shfl_xor_sync(0xffffffffu, acc, off);
    if (lane == 0) g_z[seg * C + c] = acc + b1[c];
}

// ---------------- K4: tf32 mma.sync GEMM, cp.async double-buffered ---------
#define BM 128
#define BN 128

__device__ __forceinline__ int sidx(int r, int k) {
    return r * 32 + (k ^ ((r & 7) * 4));
}

__global__ __launch_bounds__(256, 2) void k_mm(const float* __restrict__ x,
                                               const int* __restrict__ o,
                                               float* __restrict__ h) {
    extern __shared__ __align__(128) float smem[];  // 16384 floats = 64KB
    __shared__ int so[NS];
    __shared__ float shbn[512];

    uint32_t sb = s2u(smem);
    int tid = threadIdx.x;
    int w = tid >> 5, lane = tid & 31;
    int l4 = lane >> 2, lm4 = lane & 3;
    int wm = (w & 1) * 64;
    int wn = (w >> 1) * 32;
    int r0 = blockIdx.y * BM;
    int c0 = blockIdx.x * BN;

    if (tid < NS) so[tid] = o[tid];
    shbn[tid] = 0.f;
    shbn[tid + 256] = 0.f;

    auto stage = [&](int kt) {
        int buf = kt & 1;
        const float* xs = x + (size_t)r0 * C + kt * 32;
        const float* ws = g_wt + (size_t)c0 * C + kt * 32;
        uint32_t ab = sb + buf * 16384;
        uint32_t bb = sb + 32768 + buf * 16384;
        #pragma unroll
        for (int i = 0; i < 4; i++) {
            int cid = tid + i * 256;
            int row = cid >> 3, c16 = cid & 7;
            uint32_t off = row * 128 + ((c16 * 16) ^ ((row & 7) * 16));
            cpa16(ab + off, xs + (size_t)row * C + c16 * 4);
            cpa16(bb + off, ws + (size_t)row * C + c16 * 4);
        }
        asm volatile("cp.async.commit_group;" ::: "memory");
    };

    float acc[4][4][4] = {};
    stage(0);

    for (int kt = 0; kt < 8; kt++) {
        if (kt < 7) {
            stage(kt + 1);
            asm volatile("cp.async.wait_group 1;" ::: "memory");
        } else {
            asm volatile("cp.async.wait_group 0;" ::: "memory");
        }
        __syncthreads();

        const float* A = smem + (kt & 1) * 4096;
        const float* B = smem + 8192 + (kt & 1) * 4096;

        #pragma unroll
        for (int ks = 0; ks < 4; ks++) {
            int kb = ks * 8 + lm4;
            unsigned af[4][4];
            unsigned bf[4][2];
            #pragma unroll
            for (int mi = 0; mi < 4; mi++) {
                int m0 = wm + mi * 16 + l4;
                af[mi][0] = tf32u(A[sidx(m0,     kb)]);
                af[mi][1] = tf32u(A[sidx(m0 + 8, kb)]);
                af[mi][2] = tf32u(A[sidx(m0,     kb + 4)]);
                af[mi][3] = tf32u(A[sidx(m0 + 8, kb + 4)]);
            }
            #pragma unroll
            for (int ni = 0; ni < 4; ni++) {
                int n = wn + ni * 8 + l4;
                bf[ni][0] = __float_as_uint(B[sidx(n, kb)]);
                bf[ni][1] = __float_as_uint(B[sidx(n, kb + 4)]);
            }
            #pragma unroll
            for (int mi = 0; mi < 4; mi++)
                #pragma unroll
                for (int ni = 0; ni < 4; ni++)
                    asm volatile(
                        "mma.sync.aligned.m16n8k8.row.col.f32.tf32.tf32.f32 "
                        "{%0,%1,%2,%3},{%4,%5,%6,%7},{%8,%9},{%0,%1,%2,%3};"
                        : "+f"(acc[mi][ni][0]), "+f"(acc[mi][ni][1]),
                          "+f"(acc[mi][ni][2]), "+f"(acc[mi][ni][3])
                        : "r"(af[mi][0]), "r"(af[mi][1]),
                          "r"(af[mi][2]), "r"(af[mi][3]),
                          "r"(bf[ni][0]), "r"(bf[ni][1]));
        }
        __syncthreads();
    }

    // ---- epilogue: + z[seg], write h, fused BN partial sums ----
    float cs[4][2] = {}, css[4][2] = {};
    #pragma unroll
    for (int mi = 0; mi < 4; mi++) {
        #pragma unroll
        for (int half = 0; half < 2; half++) {
            int r = r0 + wm + mi * 16 + l4 + half * 8;
            int seg = 0;
            #pragma unroll
            for (int s = 0; s < NS; s++) seg += (r >= so[s]);
            #pragma unroll
            for (int ni = 0; ni < 4; ni++) {
                int c = c0 + wn + ni * 8 + 2 * lm4;
                float2 z2 = *(const float2*)&g_z[seg * C + c];
                float v0 = acc[mi][ni][half * 2 + 0] + z2.x;
                float v1 = acc[mi][ni][half * 2 + 1] + z2.y;
                *(float2*)&h[(size_t)r * C + c] = make_float2(v0, v1);
                cs[ni][0] += v0;  cs[ni][1] += v1;
                css[ni][0] = fmaf(v0, v0, css[ni][0]);
                css[ni][1] = fmaf(v1, v1, css[ni][1]);
            }
        }
    }
    #pragma unroll
    for (int ni = 0; ni < 4; ni++)
        #pragma unroll
        for (int j = 0; j < 2; j++)
            #pragma unroll
            for (int off = 4; off < 32; off <<= 1) {
                cs[ni][j]  += __shfl_xor_sync(0xffffffff, cs[ni][j],  off);
                css[ni][j] += __shfl_xor_sync(0xffffffff, css[ni][j], off);
            }
    if (l4 == 0) {
        #pragma unroll
        for (int ni = 0; ni < 4; ni++) {
            int c = wn + ni * 8 + 2 * lm4;
            atomicAdd(&shbn[c],     cs[ni][0]);
            atomicAdd(&shbn[c + 1], cs[ni][1]);
            atomicAdd(&shbn[256 + c],     css[ni][0]);
            atomicAdd(&shbn[256 + c + 1], css[ni][1]);
        }
    }
    __syncthreads();
    atomicAdd(&g_bn[c0 + tid], shbn[tid]);
    atomicAdd(&g_bn[C + c0 + tid], shbn[256 + tid]);
}

// ---------------- K6: BN finalize -----------------------------------------
__global__ void k_bnfin(const float* __restrict__ gamma, const float* __restrict__ beta) {
    int t = threadIdx.x;
    float mu = g_bn[t] * (1.f / NP);
    float var = g_bn[C + t] * (1.f / NP) - mu * mu;
    float sc = gamma[t] * rsqrtf(var + 1e-5f);
    g_sc[t] = sc;
    g_sc[C + t] = beta[t] - mu * sc;
}

// ---------------- K7: out = relu(h*scale + shift), streaming --------------
__global__ void k_apply(float* __restrict__ h) {
    __shared__ float ssc[2 * C];
    int t = threadIdx.x;
    ssc[t] = g_sc[t];
    ssc[t + C] = g_sc[t + C];
    __syncthreads();
    size_t total = (size_t)NP * C / 4;
    for (size_t p = (size_t)blockIdx.x * 256 + t; p < total; p += (size_t)gridDim.x * 256) {
        float4 v = __ldcs(&((float4*)h)[p]);
        int cb = (int)((p * 4) & (C - 1));
        v.x = fmaxf(fmaf(v.x, ssc[cb + 0], ssc[C + cb + 0]), 0.f);
        v.y = fmaxf(fmaf(v.y, ssc[cb + 1], ssc[C + cb + 1]), 0.f);
        v.z = fmaxf(fmaf(v.z, ssc[cb + 2], ssc[C + cb + 2]), 0.f);
        v.w = fmaxf(fmaf(v.w, ssc[cb + 3], ssc[C + cb + 3]), 0.f);
        __stcs(&((float4*)h)[p], v);
    }
}

extern "C" void kernel_launch(void* const* d_in, const int* in_sizes, int n_in,
                              void* d_out, int out_size) {
    const float* x     = (const float*)d_in[0];
    const int*   o     = (const int*)d_in[1];
    const float* W1    = (const float*)d_in[2];
    const float* b1    = (const float*)d_in[3];
    const float* W2    = (const float*)d_in[4];
    const float* b2    = (const float*)d_in[5];
    const float* gamma = (const float*)d_in[6];
    const float* beta  = (const float*)d_in[7];
    float* h = (float*)d_out;

    static bool attr_done = false;
    if (!attr_done) {
        cudaFuncSetAttribute(k_mm, cudaFuncAttributeMaxDynamicSharedMemorySize, 65536);
        attr_done = true;
    }

    k_segsum<<<NS * 32, 256>>>(x, o);
    k_wt<<<dim3(8, 8), dim3(32, 8)>>>(W1);     // also zeroes g_bn (before k_mm)
    k_mlp1<<<NS * 32, 256>>>(o, W2, b2);
    k_mlp2<<<NS * 32, 256>>>(W1, b1);
    dim3 g(C / BN, NP / BM);
    k_mm<<<g, 256, 65536>>>(x, o, h);
    k_bnfin<<<1, 256>>>(gamma, beta);
    k_apply<<<4096, 256>>>(h);
}